// round 8
// baseline (speedup 1.0000x reference)
#include <cuda_runtime.h>
#include <cuda_bf16.h>
#include <math.h>

#define BATCH 4
#define CH 128
#define NTOK 4096            // H*W
#define M_ROWS (BATCH*NTOK)  // 16384
#define HEADS 4
#define HD 32
#define HIDDEN 256
#define EPS 1e-5f

// q pre-scale: (1/sqrt(32)) * log2(e)  -> softmax done in exp2 domain
#define QSC (0.17677669529663689f * 1.4426950408889634f)

// ---------------- scratch (device globals; no allocation) ----------------
__device__ __nv_bfloat16  g_xln [M_ROWS * CH];
__device__ float          g_xtok[M_ROWS * CH];
__device__ __nv_bfloat16  g_qkv [M_ROWS * 3 * CH];
__device__ __nv_bfloat16  g_vT  [BATCH * HEADS * HD * NTOK];
__device__ __nv_bfloat16  g_attn[M_ROWS * CH];
__device__ float          g_x2  [M_ROWS * CH];
__device__ __nv_bfloat16  g_hdn [M_ROWS * HIDDEN];
__device__ __nv_bfloat16  g_wqkv[3 * CH * CH];
__device__ __nv_bfloat16  g_wproj[CH * CH];
__device__ __nv_bfloat16  g_wfc1[HIDDEN * CH];
__device__ __nv_bfloat16  g_wfc2[CH * HIDDEN];

__device__ __forceinline__ unsigned ex2b(unsigned x) {
    unsigned r;
    asm("ex2.approx.ftz.bf16x2 %0, %1;" : "=r"(r) : "r"(x));
    return r;
}

__device__ __forceinline__ unsigned smem_u32(const void* p) {
    return (unsigned)__cvta_generic_to_shared(p);
}

#define CP16(dst, src) \
    asm volatile("cp.async.cg.shared.global [%0], [%1], 16;" :: "r"(dst), "l"(src))
#define CPCOMMIT() asm volatile("cp.async.commit_group;")
#define CPWAIT0()  asm volatile("cp.async.wait_group 0;")
#define CPWAIT1()  asm volatile("cp.async.wait_group 1;")

#define LDSM4(r0, r1, r2, r3, addr) \
    asm volatile("ldmatrix.sync.aligned.m8n8.x4.shared.b16 {%0,%1,%2,%3}, [%4];" \
                 : "=r"(r0), "=r"(r1), "=r"(r2), "=r"(r3) : "r"(addr))

__device__ __forceinline__ void mma16816(float d[4], const unsigned a[4],
                                         unsigned b0, unsigned b1) {
    asm volatile(
        "mma.sync.aligned.m16n8k16.row.col.f32.bf16.bf16.f32 "
        "{%0,%1,%2,%3}, {%4,%5,%6,%7}, {%8,%9}, {%0,%1,%2,%3};"
        : "+f"(d[0]), "+f"(d[1]), "+f"(d[2]), "+f"(d[3])
        : "r"(a[0]), "r"(a[1]), "r"(a[2]), "r"(a[3]), "r"(b0), "r"(b1));
}

// ---------------- weight fp32->bf16 conversion -----------
__global__ void wconv_kernel(const float* __restrict__ qkv_w,
                             const float* __restrict__ proj_w,
                             const float* __restrict__ fc1_w,
                             const float* __restrict__ fc2_w) {
    int i = blockIdx.x * 256 + threadIdx.x;
    if (i < 49152)       g_wqkv[i]          = __float2bfloat16(qkv_w[i]);
    else if (i < 65536)  g_wproj[i - 49152] = __float2bfloat16(proj_w[i - 49152]);
    else if (i < 98304)  g_wfc1[i - 65536]  = __float2bfloat16(fc1_w[i - 65536]);
    else if (i < 131072) g_wfc2[i - 98304]  = __float2bfloat16(fc2_w[i - 98304]);
}

// ---------------- LN1: NCHW -> [token, C]; also raw x token-major --------
__global__ void ln1_kernel(const float* __restrict__ x,
                           const float* __restrict__ w,
                           const float* __restrict__ bgain) {
    __shared__ float s[CH][33];
    __shared__ float ps[8][32], pq[8][32];
    __shared__ float mu_s[32], rs_s[32];

    int b  = blockIdx.x >> 7;
    int n0 = (blockIdx.x & 127) * 32;
    int tx = threadIdx.x & 31;
    int ty = threadIdx.x >> 5;

    const float* xb = x + (size_t)b * CH * NTOK + n0;
    float sum = 0.f, sq = 0.f;
#pragma unroll
    for (int c = ty; c < CH; c += 8) {
        float v = xb[(size_t)c * NTOK + tx];
        s[c][tx] = v;
        sum += v; sq += v * v;
    }
    ps[ty][tx] = sum; pq[ty][tx] = sq;
    __syncthreads();
    if (ty == 0) {
        float S = 0.f, Q = 0.f;
#pragma unroll
        for (int i = 0; i < 8; i++) { S += ps[i][tx]; Q += pq[i][tx]; }
        float mu  = S * (1.0f / CH);
        float var = Q * (1.0f / CH) - mu * mu;
        mu_s[tx] = mu;
        rs_s[tx] = rsqrtf(var + EPS);
    }
    __syncthreads();
    __nv_bfloat16* out = g_xln + ((size_t)b * NTOK + n0) * CH;
    float* outraw = g_xtok + ((size_t)b * NTOK + n0) * CH;
    for (int idx = threadIdx.x; idx < 32 * CH; idx += 256) {
        int t = idx >> 7, c = idx & 127;
        float raw = s[c][t];
        outraw[idx] = raw;
        out[idx] = __float2bfloat16((raw - mu_s[t]) * rs_s[t] * w[c] + bgain[c]);
    }
}

// ---------------- LN2: fp32 x2 -> bf16 xln ----------------
__global__ void ln2_kernel(const float* __restrict__ w,
                           const float* __restrict__ bb) {
    int warp = (blockIdx.x * blockDim.x + threadIdx.x) >> 5;
    int lane = threadIdx.x & 31;
    if (warp >= M_ROWS) return;
    const float4* xp = (const float4*)(g_x2 + (size_t)warp * CH);
    float4 v = xp[lane];
    float sum = v.x + v.y + v.z + v.w;
    float sq  = v.x*v.x + v.y*v.y + v.z*v.z + v.w*v.w;
#pragma unroll
    for (int off = 16; off > 0; off >>= 1) {
        sum += __shfl_xor_sync(0xffffffffu, sum, off);
        sq  += __shfl_xor_sync(0xffffffffu, sq,  off);
    }
    float mu  = sum * (1.0f / CH);
    float var = sq  * (1.0f / CH) - mu * mu;
    float rs  = rsqrtf(var + EPS);
    float4 wv = ((const float4*)w)[lane];
    float4 bv = ((const float4*)bb)[lane];
    __nv_bfloat162 o01 = __floats2bfloat162_rn((v.x - mu) * rs * wv.x + bv.x,
                                               (v.y - mu) * rs * wv.y + bv.y);
    __nv_bfloat162 o23 = __floats2bfloat162_rn((v.z - mu) * rs * wv.z + bv.z,
                                               (v.w - mu) * rs * wv.w + bv.w);
    uint2 pk;
    pk.x = *(unsigned*)&o01;
    pk.y = *(unsigned*)&o23;
    *(uint2*)(g_xln + (size_t)warp * CH + lane * 4) = pk;
}

// ---------------- tensor-core GEMM: C = A[M,K]bf16 * W[N,K]bf16^T --------
template<int EPI>
__global__ __launch_bounds__(256)
void gemm_tc(const __nv_bfloat16* __restrict__ A,
             const __nv_bfloat16* __restrict__ W,
             const float* __restrict__ bias,
             const float* __restrict__ res,
             float* __restrict__ C, int K) {
    __shared__ __nv_bfloat16 As[128][40];
    __shared__ __nv_bfloat16 Ws[64][40];

    int m0 = blockIdx.y * 128;
    int n0 = blockIdx.x * 64;
    int tid  = threadIdx.x;
    int warp = tid >> 5;
    int lane = tid & 31;
    int g = lane >> 2;
    int t = lane & 3;
    int warp_m = warp >> 1;
    int warp_n = warp & 1;

    float acc[2][4][4];
#pragma unroll
    for (int i = 0; i < 2; i++)
#pragma unroll
        for (int j = 0; j < 4; j++)
#pragma unroll
            for (int c = 0; c < 4; c++) acc[i][j][c] = 0.f;

    int arow = tid >> 2, achk = tid & 3;

    for (int k0 = 0; k0 < K; k0 += 32) {
        __syncthreads();
        *(float4*)&As[arow][achk * 8] =
            *(const float4*)(A + (size_t)(m0 + arow) * K + k0 + achk * 8);
        *(float4*)&As[arow + 64][achk * 8] =
            *(const float4*)(A + (size_t)(m0 + arow + 64) * K + k0 + achk * 8);
        *(float4*)&Ws[arow][achk * 8] =
            *(const float4*)(W + (size_t)(n0 + arow) * K + k0 + achk * 8);
        __syncthreads();

#pragma unroll
        for (int kk = 0; kk < 2; kk++) {
            unsigned af[2][4];
#pragma unroll
            for (int i = 0; i < 2; i++) {
                int r = warp_m * 32 + i * 16 + g;
                af[i][0] = *(const unsigned*)&As[r][kk * 16 + 2 * t];
                af[i][1] = *(const unsigned*)&As[r + 8][kk * 16 + 2 * t];
                af[i][2] = *(const unsigned*)&As[r][kk * 16 + 2 * t + 8];
                af[i][3] = *(const unsigned*)&As[r + 8][kk * 16 + 2 * t + 8];
            }
#pragma unroll
            for (int j = 0; j < 4; j++) {
                int wr = warp_n * 32 + j * 8 + g;
                unsigned b0 = *(const unsigned*)&Ws[wr][kk * 16 + 2 * t];
                unsigned b1 = *(const unsigned*)&Ws[wr][kk * 16 + 2 * t + 8];
                mma16816(acc[0][j], af[0], b0, b1);
                mma16816(acc[1][j], af[1], b0, b1);
            }
        }
    }

    // ---- epilogue ----
#pragma unroll
    for (int i = 0; i < 2; i++) {
#pragma unroll
        for (int j = 0; j < 4; j++) {
            int col = n0 + warp_n * 32 + j * 8 + 2 * t;
#pragma unroll
            for (int half = 0; half < 2; half++) {
                int row = m0 + warp_m * 32 + i * 16 + g + half * 8;
                float v0 = acc[i][j][2 * half + 0];
                float v1 = acc[i][j][2 * half + 1];
                int b = row >> 12;
                int n = row & (NTOK - 1);
                if (EPI == 0) {
                    if (col < CH) {
                        __nv_bfloat162 p = __floats2bfloat162_rn(v0 * QSC, v1 * QSC);
                        *(__nv_bfloat162*)&g_qkv[(size_t)row * (3 * CH) + col] = p;
                    } else if (col < 2 * CH) {
                        __nv_bfloat162 p = __floats2bfloat162_rn(v0, v1);
                        *(__nv_bfloat162*)&g_qkv[(size_t)row * (3 * CH) + col] = p;
                    } else {
                        int hh = (col - 2 * CH) >> 5;
                        int d  = (col - 2 * CH) & 31;
                        size_t base = (((size_t)(b * HEADS + hh)) * HD + d) * NTOK + n;
                        g_vT[base]        = __float2bfloat16(v0);
                        g_vT[base + NTOK] = __float2bfloat16(v1);
                    }
                } else if (EPI == 1) {
                    float2 rv = *(const float2*)&res[(size_t)row * CH + col];
                    float r0 = v0 + bias[col] + rv.x;
                    float r1 = v1 + bias[col + 1] + rv.y;
                    *(float2*)&C[(size_t)row * CH + col] = make_float2(r0, r1);
                } else if (EPI == 2) {
                    float r0 = v0 + bias[col];
                    float r1 = v1 + bias[col + 1];
                    r0 = 0.5f * r0 * (1.0f + erff(r0 * 0.70710678118654752f));
                    r1 = 0.5f * r1 * (1.0f + erff(r1 * 0.70710678118654752f));
                    __nv_bfloat162 p = __floats2bfloat162_rn(r0, r1);
                    *(__nv_bfloat162*)&g_hdn[(size_t)row * HIDDEN + col] = p;
                } else { // EPI == 3
                    float r0 = v0 + bias[col] + res[(size_t)row * CH + col];
                    float r1 = v1 + bias[col + 1] + res[(size_t)row * CH + col + 1];
                    C[((size_t)(b * CH) + col) * NTOK + n] = r0;
                    C[((size_t)(b * CH) + col + 1) * NTOK + n] = r1;
                }
            }
        }
    }
}

// ---------------- flash attention: software-pipelined, 3-stage ring ------
// Bq=128, 256 threads (8 warps x 16 query rows). Per iter: S(tile j+1)
// interleaved with PV(tile j); pa overwritten in place after consumption.
// l via constant ones-column B-fragments (hoisted out of the loop).
#define NT (NTOK / 64)   // 64 key tiles

__device__ __forceinline__ void s_frags_to_pa(
    unsigned kb, const unsigned qa[2][4], unsigned pa[4][4]) {
#pragma unroll
    for (int jp = 0; jp < 4; jp++) {
        unsigned f0[4], f1[4];
        LDSM4(f0[0], f0[1], f0[2], f0[3], kb + jp * 1280);
        LDSM4(f1[0], f1[1], f1[2], f1[3], kb + jp * 1280 + 32);
#pragma unroll
        for (int jj = 0; jj < 2; jj++) {
            float s4[4] = {0.f, 0.f, 0.f, 0.f};
            mma16816(s4, qa[0], f0[2 * jj], f0[2 * jj + 1]);
            mma16816(s4, qa[1], f1[2 * jj], f1[2 * jj + 1]);
            __nv_bfloat162 lo = __floats2bfloat162_rn(s4[0], s4[1]);
            __nv_bfloat162 hi = __floats2bfloat162_rn(s4[2], s4[3]);
            pa[jp][2 * jj]     = ex2b(*(unsigned*)&lo);
            pa[jp][2 * jj + 1] = ex2b(*(unsigned*)&hi);
        }
    }
}

__global__ __launch_bounds__(256, 3)
void attn_mma_kernel() {
    __shared__ __nv_bfloat16 Ks[3][64][40];   // [slot][key][dim]
    __shared__ __nv_bfloat16 VT[3][40][72];   // [slot][dim][key]; dims 32..39: ones+zeros

    int bh = blockIdx.y;
    int b  = bh >> 2;
    int h  = bh & 3;
    int q0 = blockIdx.x * 128;
    int tid  = threadIdx.x;
    int warp = tid >> 5;
    int lane = tid & 31;
    int g = lane >> 2;
    int t = lane & 3;

    // init constant dims 32..39 of slot 0 only (vone is loaded once from it)
    for (int idx = tid; idx < 8 * 72; idx += 256) {
        int rr = idx / 72;
        int cc = idx % 72;
        VT[0][32 + rr][cc] = __float2bfloat16(rr == 0 ? 1.0f : 0.0f);
    }

    // ---- Q a-fragments ----
    unsigned qa[2][4];
    {
        const __nv_bfloat16* qp0 =
            g_qkv + (size_t)(b * NTOK + q0 + warp * 16 + g) * (3 * CH) + h * HD;
        const __nv_bfloat16* qp1 = qp0 + (size_t)8 * (3 * CH);
#pragma unroll
        for (int kk = 0; kk < 2; kk++) {
            qa[kk][0] = *(const unsigned*)(qp0 + kk * 16 + 2 * t);
            qa[kk][1] = *(const unsigned*)(qp1 + kk * 16 + 2 * t);
            qa[kk][2] = *(const unsigned*)(qp0 + kk * 16 + 2 * t + 8);
            qa[kk][3] = *(const unsigned*)(qp1 + kk * 16 + 2 * t + 8);
        }
    }

    // ---- cp.async loader mapping (1x 16B K + 1x 16B V per thread/tile) ----
    int lkey = tid >> 2, lpart = tid & 3;
    int ld   = tid >> 3, lc    = tid & 7;
    const __nv_bfloat16* kgm =
        g_qkv + (size_t)(b * NTOK + lkey) * (3 * CH) + CH + h * HD + lpart * 8;
    const __nv_bfloat16* vgm =
        g_vT + ((size_t)bh * HD + ld) * NTOK + lc * 8;
    unsigned ksdst[3], vtdst[3];
#pragma unroll
    for (int s = 0; s < 3; s++) {
        ksdst[s] = smem_u32(&Ks[s][lkey][lpart * 8]);
        vtdst[s] = smem_u32(&VT[s][ld][lc * 8]);
    }

    // ---- ldmatrix per-lane base addresses ----
    int q2 = lane >> 3, r8 = lane & 7;
    unsigned ks_lm[3], vt_lm[3];
    ks_lm[0] = smem_u32(&Ks[0][8 * (q2 >> 1) + r8][8 * (q2 & 1)]);
    vt_lm[0] = smem_u32(&VT[0][8 * (q2 >> 1) + r8][8 * (q2 & 1)]);
    unsigned v1_lm = smem_u32(&VT[0][32 + r8][16 * (q2 >> 1) + 8 * (q2 & 1)]);
#pragma unroll
    for (int s = 1; s < 3; s++) {
        ks_lm[s] = ks_lm[s - 1] + 64 * 40 * 2;
        vt_lm[s] = vt_lm[s - 1] + 40 * 72 * 2;
    }

    // ---- prologue: tiles 0 and 1 in flight ----
    CP16(ksdst[0], kgm);
    CP16(vtdst[0], vgm);
    CPCOMMIT();
    CP16(ksdst[1], kgm + (size_t)64 * (3 * CH));
    CP16(vtdst[1], vgm + 64);
    CPCOMMIT();

    float oc[5][4] = {};
    unsigned pa[4][4];
    unsigned vone[8];

    CPWAIT1();            // tile 0 arrived (ones rows also visible)
    __syncthreads();
    // constant ones B-fragments (same every tile)
    LDSM4(vone[0], vone[1], vone[2], vone[3], v1_lm);
    LDSM4(vone[4], vone[5], vone[6], vone[7], v1_lm + 64);
    s_frags_to_pa(ks_lm[0], qa, pa);

    int cur = 0, nxt = 1, sld = 2;

    for (int j = 0; j < NT - 1; j++) {
        CPWAIT0();        // tile j+1 arrived
        __syncthreads();  // all warps past iter j-1 reads of slot sld
        if (j + 2 < NT) {
            CP16(ksdst[sld], kgm + (size_t)(j + 2) * 64 * (3 * CH));
            CP16(vtdst[sld], vgm + (j + 2) * 64);
            CPCOMMIT();
        }
        unsigned kbn = ks_lm[nxt];
        unsigned vb  = vt_lm[cur];

        // ---- interleaved: PV(j)+l(j) consume pa[jp]; S(j+1) refills it ----
#pragma unroll
        for (int jp = 0; jp < 4; jp++) {
            unsigned f0[4], f1[4], m0[4], m1[4];
            LDSM4(f0[0], f0[1], f0[2], f0[3], kbn + jp * 1280);
            LDSM4(f1[0], f1[1], f1[2], f1[3], kbn + jp * 1280 + 32);
            LDSM4(m0[0], m0[1], m0[2], m0[3], vb + jp * 32);
            LDSM4(m1[0], m1[1], m1[2], m1[3], vb + 2304 + jp * 32);

            float s4a[4] = {0.f, 0.f, 0.f, 0.f};
            float s4b[4] = {0.f, 0.f, 0.f, 0.f};
            mma16816(s4a, qa[0], f0[0], f0[1]);
            mma16816(oc[0], pa[jp], m0[0], m0[1]);
            mma16816(s4a, qa[1], f1[0], f1[1]);
            mma16816(oc[1], pa[jp], m0[2], m0[3]);
            mma16816(s4b, qa[0], f0[2], f0[3]);
            mma16816(oc[2], pa[jp], m1[0], m1[1]);
            mma16816(s4b, qa[1], f1[2], f1[3]);
            mma16816(oc[3], pa[jp], m1[2], m1[3]);
            mma16816(oc[4], pa[jp], vone[2 * jp], vone[2 * jp + 1]);

            __nv_bfloat162 lo = __floats2bfloat162_rn(s4a[0], s4a[1]);
            __nv_bfloat162 hi = __floats2bfloat162_rn(s4a[2], s4a[3]);
            pa[jp][0] = ex2b(*(unsigned*)&lo);
            pa[jp][1] = ex2b(*(unsigned*)&hi);
            lo = __floats2bfloat162_rn(s4b[0], s4b[1]);
            hi = __floats2bfloat162_rn(s4b[2], s4b[3]);
            pa[jp][2] = ex2b(*(unsigned*)&lo);
            pa[jp][3] = ex2b(*(unsigned*)&hi);
        }

        int tmp = cur; cur = nxt; nxt = sld; sld = tmp;
    }

    // ---- epilogue: PV + l of last tile ----
    {
        unsigned vb = vt_lm[cur];
#pragma unroll
        for (int jp = 0; jp < 4; jp++) {
            unsigned m0[4], m1[4];
            LDSM4(m0[0], m0[1], m0[2], m0[3], vb + jp * 32);
            LDSM4(m1[0], m1[1], m1[2], m1[3], vb + 2304 + jp * 32);
            mma16816(oc[0], pa[jp], m0[0], m0[1]);
            mma16816(oc[1], pa[jp], m0[2], m0[3]);
            mma16816(oc[2], pa[jp], m1[0], m1[1]);
            mma16816(oc[3], pa[jp], m1[2], m1[3]);
            mma16816(oc[4], pa[jp], vone[2 * jp], vone[2 * jp + 1]);
        }
    }

    // l lives in column 0 of the ones d-tile -> lanes with t==0; broadcast
    float l0 = __shfl_sync(0xffffffffu, oc[4][0], lane & ~3);
    float l1 = __shfl_sync(0xffffffffu, oc[4][2], lane & ~3);
    float inv0 = 1.0f / l0;
    float inv1 = 1.0f / l1;

    __nv_bfloat16* op0 = g_attn + (size_t)(b * NTOK + q0 + warp * 16 + g) * CH + h * HD;
    __nv_bfloat16* op1 = op0 + (size_t)8 * CH;
#pragma unroll
    for (int jd = 0; jd < 4; jd++) {
        __nv_bfloat162 r0 = __floats2bfloat162_rn(oc[jd][0] * inv0, oc[jd][1] * inv0);
        __nv_bfloat162 r1 = __floats2bfloat162_rn(oc[jd][2] * inv1, oc[jd][3] * inv1);
        *(__nv_bfloat162*)(op0 + 8 * jd + 2 * t) = r0;
        *(__nv_bfloat162*)(op1 + 8 * jd + 2 * t) = r1;
    }
}

// ---------------- launch ----------------
extern "C" void kernel_launch(void* const* d_in, const int* in_sizes, int n_in,
                              void* d_out, int out_size) {
    const float* x      = (const float*)d_in[0];
    const float* ln1_w  = (const float*)d_in[1];
    const float* ln1_b  = (const float*)d_in[2];
    const float* qkv_w  = (const float*)d_in[3];
    const float* proj_w = (const float*)d_in[4];
    const float* proj_b = (const float*)d_in[5];
    const float* ln2_w  = (const float*)d_in[6];
    const float* ln2_b  = (const float*)d_in[7];
    const float* fc1_w  = (const float*)d_in[8];
    const float* fc1_b  = (const float*)d_in[9];
    const float* fc2_w  = (const float*)d_in[10];
    const float* fc2_b  = (const float*)d_in[11];
    float* out = (float*)d_out;

    void *p_xln, *p_xtok, *p_attn, *p_x2, *p_hdn;
    void *p_wqkv, *p_wproj, *p_wfc1, *p_wfc2;
    cudaGetSymbolAddress(&p_xln,  g_xln);
    cudaGetSymbolAddress(&p_xtok, g_xtok);
    cudaGetSymbolAddress(&p_attn, g_attn);
    cudaGetSymbolAddress(&p_x2,   g_x2);
    cudaGetSymbolAddress(&p_hdn,  g_hdn);
    cudaGetSymbolAddress(&p_wqkv, g_wqkv);
    cudaGetSymbolAddress(&p_wproj, g_wproj);
    cudaGetSymbolAddress(&p_wfc1, g_wfc1);
    cudaGetSymbolAddress(&p_wfc2, g_wfc2);
    __nv_bfloat16* xln  = (__nv_bfloat16*)p_xln;
    float*         xtok = (float*)p_xtok;
    __nv_bfloat16* attn = (__nv_bfloat16*)p_attn;
    float*         x2   = (float*)p_x2;
    __nv_bfloat16* hdn  = (__nv_bfloat16*)p_hdn;
    __nv_bfloat16* wqkv = (__nv_bfloat16*)p_wqkv;
    __nv_bfloat16* wproj= (__nv_bfloat16*)p_wproj;
    __nv_bfloat16* wfc1 = (__nv_bfloat16*)p_wfc1;
    __nv_bfloat16* wfc2 = (__nv_bfloat16*)p_wfc2;

    // 0. weights -> bf16
    wconv_kernel<<<512, 256>>>(qkv_w, proj_w, fc1_w, fc2_w);

    // 1. LN1 (NCHW -> token-major bf16 + raw fp32 copy)
    ln1_kernel<<<BATCH * (NTOK / 32), 256>>>(x, ln1_w, ln1_b);

    // 2. QKV gemm (tensor cores) -> q/k in g_qkv, v in g_vT
    gemm_tc<0><<<dim3(3 * CH / 64, M_ROWS / 128), 256>>>(
        xln, wqkv, nullptr, nullptr, nullptr, CH);

    // 3. flash attention -> g_attn bf16
    attn_mma_kernel<<<dim3(NTOK / 128, BATCH * HEADS), 256>>>();

    // 4. proj + residual(x token-major) -> x2 fp32
    gemm_tc<1><<<dim3(CH / 64, M_ROWS / 128), 256>>>(
        attn, wproj, proj_b, xtok, x2, CH);

    // 5. LN2 -> xln bf16
    ln2_kernel<<<(M_ROWS * 32 + 255) / 256, 256>>>(ln2_w, ln2_b);

    // 6. fc1 + bias + gelu -> hdn bf16
    gemm_tc<2><<<dim3(HIDDEN / 64, M_ROWS / 128), 256>>>(
        xln, wfc1, fc1_b, nullptr, nullptr, CH);

    // 7. fc2 + bias + residual(x2) -> out (NCHW fp32)
    gemm_tc<3><<<dim3(CH / 64, M_ROWS / 128), 256>>>(
        hdn, wfc2, fc2_b, x2, out, HIDDEN);
}

// round 9
// speedup vs baseline: 1.1166x; 1.1166x over previous
#include <cuda_runtime.h>
#include <cuda_bf16.h>
#include <math.h>

#define BATCH 4
#define CH 128
#define NTOK 4096            // H*W
#define M_ROWS (BATCH*NTOK)  // 16384
#define HEADS 4
#define HD 32
#define HIDDEN 256
#define EPS 1e-5f

// q pre-scale: (1/sqrt(32)) * log2(e)  -> softmax done in exp2 domain
#define QSC (0.17677669529663689f * 1.4426950408889634f)

// ---------------- scratch (device globals; no allocation) ----------------
__device__ __nv_bfloat16  g_xln [M_ROWS * CH];
__device__ float          g_xtok[M_ROWS * CH];
__device__ __nv_bfloat16  g_qkv [M_ROWS * 3 * CH];
__device__ __nv_bfloat16  g_vT  [BATCH * HEADS * HD * NTOK];
__device__ __nv_bfloat16  g_attn[M_ROWS * CH];
__device__ float          g_x2  [M_ROWS * CH];
__device__ __nv_bfloat16  g_hdn [M_ROWS * HIDDEN];
__device__ __nv_bfloat16  g_wqkv[3 * CH * CH];
__device__ __nv_bfloat16  g_wproj[CH * CH];
__device__ __nv_bfloat16  g_wfc1[HIDDEN * CH];
__device__ __nv_bfloat16  g_wfc2[CH * HIDDEN];

__device__ __forceinline__ unsigned ex2b(unsigned x) {
    unsigned r;
    asm("ex2.approx.ftz.bf16x2 %0, %1;" : "=r"(r) : "r"(x));
    return r;
}

__device__ __forceinline__ unsigned smem_u32(const void* p) {
    return (unsigned)__cvta_generic_to_shared(p);
}

#define CP16(dst, src) \
    asm volatile("cp.async.cg.shared.global [%0], [%1], 16;" :: "r"(dst), "l"(src))
#define CPCOMMIT() asm volatile("cp.async.commit_group;")
#define CPWAIT0()  asm volatile("cp.async.wait_group 0;")

#define LDSM4(r0, r1, r2, r3, addr) \
    asm volatile("ldmatrix.sync.aligned.m8n8.x4.shared.b16 {%0,%1,%2,%3}, [%4];" \
                 : "=r"(r0), "=r"(r1), "=r"(r2), "=r"(r3) : "r"(addr))

__device__ __forceinline__ void mma16816(float d[4], const unsigned a[4],
                                         unsigned b0, unsigned b1) {
    asm volatile(
        "mma.sync.aligned.m16n8k16.row.col.f32.bf16.bf16.f32 "
        "{%0,%1,%2,%3}, {%4,%5,%6,%7}, {%8,%9}, {%0,%1,%2,%3};"
        : "+f"(d[0]), "+f"(d[1]), "+f"(d[2]), "+f"(d[3])
        : "r"(a[0]), "r"(a[1]), "r"(a[2]), "r"(a[3]), "r"(b0), "r"(b1));
}

// ---------------- weight fp32->bf16 conversion -----------
__global__ void wconv_kernel(const float* __restrict__ qkv_w,
                             const float* __restrict__ proj_w,
                             const float* __restrict__ fc1_w,
                             const float* __restrict__ fc2_w) {
    int i = blockIdx.x * 256 + threadIdx.x;
    if (i < 49152)       g_wqkv[i]          = __float2bfloat16(qkv_w[i]);
    else if (i < 65536)  g_wproj[i - 49152] = __float2bfloat16(proj_w[i - 49152]);
    else if (i < 98304)  g_wfc1[i - 65536]  = __float2bfloat16(fc1_w[i - 65536]);
    else if (i < 131072) g_wfc2[i - 98304]  = __float2bfloat16(fc2_w[i - 98304]);
}

// ---------------- LN1: NCHW -> [token, C]; also raw x token-major --------
__global__ void ln1_kernel(const float* __restrict__ x,
                           const float* __restrict__ w,
                           const float* __restrict__ bgain) {
    __shared__ float s[CH][33];
    __shared__ float ps[8][32], pq[8][32];
    __shared__ float mu_s[32], rs_s[32];

    int b  = blockIdx.x >> 7;
    int n0 = (blockIdx.x & 127) * 32;
    int tx = threadIdx.x & 31;
    int ty = threadIdx.x >> 5;

    const float* xb = x + (size_t)b * CH * NTOK + n0;
    float sum = 0.f, sq = 0.f;
#pragma unroll
    for (int c = ty; c < CH; c += 8) {
        float v = xb[(size_t)c * NTOK + tx];
        s[c][tx] = v;
        sum += v; sq += v * v;
    }
    ps[ty][tx] = sum; pq[ty][tx] = sq;
    __syncthreads();
    if (ty == 0) {
        float S = 0.f, Q = 0.f;
#pragma unroll
        for (int i = 0; i < 8; i++) { S += ps[i][tx]; Q += pq[i][tx]; }
        float mu  = S * (1.0f / CH);
        float var = Q * (1.0f / CH) - mu * mu;
        mu_s[tx] = mu;
        rs_s[tx] = rsqrtf(var + EPS);
    }
    __syncthreads();
    __nv_bfloat16* out = g_xln + ((size_t)b * NTOK + n0) * CH;
    float* outraw = g_xtok + ((size_t)b * NTOK + n0) * CH;
    for (int idx = threadIdx.x; idx < 32 * CH; idx += 256) {
        int t = idx >> 7, c = idx & 127;
        float raw = s[c][t];
        outraw[idx] = raw;
        out[idx] = __float2bfloat16((raw - mu_s[t]) * rs_s[t] * w[c] + bgain[c]);
    }
}

// ---------------- tensor-core GEMM: C = A[M,K]bf16 * W[N,K]bf16^T --------
// BM=128, BN=64, BK=32, 256 threads (8 warps, 4x2), warp tile 32x32
// EPI: 0=qkv, 2=fc1(bias+gelu), 3=fc2(bias+res+NCHW out)
template<int EPI>
__global__ __launch_bounds__(256)
void gemm_tc(const __nv_bfloat16* __restrict__ A,
             const __nv_bfloat16* __restrict__ W,
             const float* __restrict__ bias,
             const float* __restrict__ res,
             float* __restrict__ C, int K) {
    __shared__ __nv_bfloat16 As[128][40];
    __shared__ __nv_bfloat16 Ws[64][40];

    int m0 = blockIdx.y * 128;
    int n0 = blockIdx.x * 64;
    int tid  = threadIdx.x;
    int warp = tid >> 5;
    int lane = tid & 31;
    int g = lane >> 2;
    int t = lane & 3;
    int warp_m = warp >> 1;
    int warp_n = warp & 1;

    float acc[2][4][4];
#pragma unroll
    for (int i = 0; i < 2; i++)
#pragma unroll
        for (int j = 0; j < 4; j++)
#pragma unroll
            for (int c = 0; c < 4; c++) acc[i][j][c] = 0.f;

    int arow = tid >> 2, achk = tid & 3;

    for (int k0 = 0; k0 < K; k0 += 32) {
        __syncthreads();
        *(float4*)&As[arow][achk * 8] =
            *(const float4*)(A + (size_t)(m0 + arow) * K + k0 + achk * 8);
        *(float4*)&As[arow + 64][achk * 8] =
            *(const float4*)(A + (size_t)(m0 + arow + 64) * K + k0 + achk * 8);
        *(float4*)&Ws[arow][achk * 8] =
            *(const float4*)(W + (size_t)(n0 + arow) * K + k0 + achk * 8);
        __syncthreads();

#pragma unroll
        for (int kk = 0; kk < 2; kk++) {
            unsigned af[2][4];
#pragma unroll
            for (int i = 0; i < 2; i++) {
                int r = warp_m * 32 + i * 16 + g;
                af[i][0] = *(const unsigned*)&As[r][kk * 16 + 2 * t];
                af[i][1] = *(const unsigned*)&As[r + 8][kk * 16 + 2 * t];
                af[i][2] = *(const unsigned*)&As[r][kk * 16 + 2 * t + 8];
                af[i][3] = *(const unsigned*)&As[r + 8][kk * 16 + 2 * t + 8];
            }
#pragma unroll
            for (int j = 0; j < 4; j++) {
                int wr = warp_n * 32 + j * 8 + g;
                unsigned b0 = *(const unsigned*)&Ws[wr][kk * 16 + 2 * t];
                unsigned b1 = *(const unsigned*)&Ws[wr][kk * 16 + 2 * t + 8];
                mma16816(acc[0][j], af[0], b0, b1);
                mma16816(acc[1][j], af[1], b0, b1);
            }
        }
    }

    // ---- epilogue ----
#pragma unroll
    for (int i = 0; i < 2; i++) {
#pragma unroll
        for (int j = 0; j < 4; j++) {
            int col = n0 + warp_n * 32 + j * 8 + 2 * t;
#pragma unroll
            for (int half = 0; half < 2; half++) {
                int row = m0 + warp_m * 32 + i * 16 + g + half * 8;
                float v0 = acc[i][j][2 * half + 0];
                float v1 = acc[i][j][2 * half + 1];
                int b = row >> 12;
                int n = row & (NTOK - 1);
                if (EPI == 0) {
                    if (col < CH) {
                        __nv_bfloat162 p = __floats2bfloat162_rn(v0 * QSC, v1 * QSC);
                        *(__nv_bfloat162*)&g_qkv[(size_t)row * (3 * CH) + col] = p;
                    } else if (col < 2 * CH) {
                        __nv_bfloat162 p = __floats2bfloat162_rn(v0, v1);
                        *(__nv_bfloat162*)&g_qkv[(size_t)row * (3 * CH) + col] = p;
                    } else {
                        int hh = (col - 2 * CH) >> 5;
                        int d  = (col - 2 * CH) & 31;
                        size_t base = (((size_t)(b * HEADS + hh)) * HD + d) * NTOK + n;
                        g_vT[base]        = __float2bfloat16(v0);
                        g_vT[base + NTOK] = __float2bfloat16(v1);
                    }
                } else if (EPI == 2) {
                    float r0 = v0 + bias[col];
                    float r1 = v1 + bias[col + 1];
                    r0 = 0.5f * r0 * (1.0f + erff(r0 * 0.70710678118654752f));
                    r1 = 0.5f * r1 * (1.0f + erff(r1 * 0.70710678118654752f));
                    __nv_bfloat162 p = __floats2bfloat162_rn(r0, r1);
                    *(__nv_bfloat162*)&g_hdn[(size_t)row * HIDDEN + col] = p;
                } else { // EPI == 3
                    float r0 = v0 + bias[col] + res[(size_t)row * CH + col];
                    float r1 = v1 + bias[col + 1] + res[(size_t)row * CH + col + 1];
                    C[((size_t)(b * CH) + col) * NTOK + n] = r0;
                    C[((size_t)(b * CH) + col + 1) * NTOK + n] = r1;
                }
            }
        }
    }
}

// ---------------- proj + residual + LN2 fused -----------------------------
// BM=64, BN=128 (full channel row per block), 256 threads, 8 warps (4x2).
// x2 = attn*Wproj^T + bias + xtok  (fp32, stored), xln = LN2(x2) (bf16).
__global__ __launch_bounds__(256)
void proj_ln_kernel(const __nv_bfloat16* __restrict__ A,
                    const __nv_bfloat16* __restrict__ W,
                    const float* __restrict__ bias,
                    const float* __restrict__ res,
                    const float* __restrict__ w2,
                    const float* __restrict__ b2) {
    __shared__ __nv_bfloat16 As[64][40];
    __shared__ __nv_bfloat16 Ws[128][40];
    __shared__ float red_s[64][2], red_q[64][2];

    int m0 = blockIdx.x * 64;
    int tid  = threadIdx.x;
    int warp = tid >> 5;
    int lane = tid & 31;
    int g = lane >> 2;
    int t = lane & 3;
    int warp_m = warp >> 1;   // 0..3 -> 16-row tiles
    int warp_n = warp & 1;    // 0..1 -> 64-col halves

    float acc[8][4];
#pragma unroll
    for (int j = 0; j < 8; j++)
#pragma unroll
        for (int c = 0; c < 4; c++) acc[j][c] = 0.f;

    int arow = tid >> 2, achk = tid & 3;

    for (int k0 = 0; k0 < CH; k0 += 32) {
        __syncthreads();
        *(float4*)&As[arow][achk * 8] =
            *(const float4*)(A + (size_t)(m0 + arow) * CH + k0 + achk * 8);
        *(float4*)&Ws[arow][achk * 8] =
            *(const float4*)(W + (size_t)arow * CH + k0 + achk * 8);
        *(float4*)&Ws[arow + 64][achk * 8] =
            *(const float4*)(W + (size_t)(arow + 64) * CH + k0 + achk * 8);
        __syncthreads();

#pragma unroll
        for (int kk = 0; kk < 2; kk++) {
            unsigned af[4];
            int r = warp_m * 16 + g;
            af[0] = *(const unsigned*)&As[r][kk * 16 + 2 * t];
            af[1] = *(const unsigned*)&As[r + 8][kk * 16 + 2 * t];
            af[2] = *(const unsigned*)&As[r][kk * 16 + 2 * t + 8];
            af[3] = *(const unsigned*)&As[r + 8][kk * 16 + 2 * t + 8];
#pragma unroll
            for (int j = 0; j < 8; j++) {
                int wr = warp_n * 64 + j * 8 + g;
                unsigned b0 = *(const unsigned*)&Ws[wr][kk * 16 + 2 * t];
                unsigned b1 = *(const unsigned*)&Ws[wr][kk * 16 + 2 * t + 8];
                mma16816(acc[j], af, b0, b1);
            }
        }
    }

    // ---- epilogue: bias + residual, per-row partial sums ----
    float s[2] = {0.f, 0.f}, q[2] = {0.f, 0.f};
#pragma unroll
    for (int j = 0; j < 8; j++) {
        int col = warp_n * 64 + j * 8 + 2 * t;
#pragma unroll
        for (int h = 0; h < 2; h++) {
            int row = m0 + warp_m * 16 + g + h * 8;
            float2 rv = *(const float2*)&res[(size_t)row * CH + col];
            float r0 = acc[j][2 * h]     + bias[col]     + rv.x;
            float r1 = acc[j][2 * h + 1] + bias[col + 1] + rv.y;
            acc[j][2 * h]     = r0;
            acc[j][2 * h + 1] = r1;
            s[h] += r0 + r1;
            q[h] += r0 * r0 + r1 * r1;
        }
    }
    // quad reduce over t (lanes g*4+t share rows)
#pragma unroll
    for (int h = 0; h < 2; h++) {
        s[h] += __shfl_xor_sync(0xffffffffu, s[h], 1);
        s[h] += __shfl_xor_sync(0xffffffffu, s[h], 2);
        q[h] += __shfl_xor_sync(0xffffffffu, q[h], 1);
        q[h] += __shfl_xor_sync(0xffffffffu, q[h], 2);
    }
    if (t == 0) {
#pragma unroll
        for (int h = 0; h < 2; h++) {
            int rl = warp_m * 16 + g + h * 8;
            red_s[rl][warp_n] = s[h];
            red_q[rl][warp_n] = q[h];
        }
    }
    __syncthreads();

    float mu[2], rs[2];
#pragma unroll
    for (int h = 0; h < 2; h++) {
        int rl = warp_m * 16 + g + h * 8;
        float S = red_s[rl][0] + red_s[rl][1];
        float Q = red_q[rl][0] + red_q[rl][1];
        mu[h] = S * (1.0f / CH);
        float var = Q * (1.0f / CH) - mu[h] * mu[h];
        rs[h] = rsqrtf(var + EPS);
    }

#pragma unroll
    for (int j = 0; j < 8; j++) {
        int col = warp_n * 64 + j * 8 + 2 * t;
        float2 wv = *(const float2*)&w2[col];
        float2 bv = *(const float2*)&b2[col];
#pragma unroll
        for (int h = 0; h < 2; h++) {
            int row = m0 + warp_m * 16 + g + h * 8;
            float r0 = acc[j][2 * h];
            float r1 = acc[j][2 * h + 1];
            *(float2*)&g_x2[(size_t)row * CH + col] = make_float2(r0, r1);
            __nv_bfloat162 p = __floats2bfloat162_rn(
                (r0 - mu[h]) * rs[h] * wv.x + bv.x,
                (r1 - mu[h]) * rs[h] * wv.y + bv.y);
            *(__nv_bfloat162*)&g_xln[(size_t)row * CH + col] = p;
        }
    }
}

// ---------------- flash attention (R5 schedule, 4 CTAs/SM) ---------------
// grid: (NTOK/128, B*HEADS), 256 threads (8 warps x 16 query rows)
// l computed via ones-column (VT dim 32 == 1.0) folded into the PV mma.
__global__ __launch_bounds__(256, 4)
void attn_mma_kernel() {
    __shared__ __nv_bfloat16 Ks[2][64][40];   // [buf][key][dim]
    __shared__ __nv_bfloat16 VT[2][40][72];   // [buf][dim][key]; dims 32..39: ones+zeros

    int bh = blockIdx.y;
    int b  = bh >> 2;
    int h  = bh & 3;
    int q0 = blockIdx.x * 128;
    int tid  = threadIdx.x;
    int warp = tid >> 5;
    int lane = tid & 31;
    int g = lane >> 2;
    int t = lane & 3;

    // init constant dims 32..39 of both VT buffers (dim 32 = 1.0, rest 0)
    for (int idx = tid; idx < 2 * 8 * 72; idx += 256) {
        int bu = idx / (8 * 72);
        int rr = (idx / 72) & 7;
        int cc = idx % 72;
        VT[bu][32 + rr][cc] = __float2bfloat16(rr == 0 ? 1.0f : 0.0f);
    }

    // ---- Q a-fragments ----
    unsigned qa[2][4];
    {
        const __nv_bfloat16* qp0 =
            g_qkv + (size_t)(b * NTOK + q0 + warp * 16 + g) * (3 * CH) + h * HD;
        const __nv_bfloat16* qp1 = qp0 + (size_t)8 * (3 * CH);
#pragma unroll
        for (int kk = 0; kk < 2; kk++) {
            qa[kk][0] = *(const unsigned*)(qp0 + kk * 16 + 2 * t);
            qa[kk][1] = *(const unsigned*)(qp1 + kk * 16 + 2 * t);
            qa[kk][2] = *(const unsigned*)(qp0 + kk * 16 + 2 * t + 8);
            qa[kk][3] = *(const unsigned*)(qp1 + kk * 16 + 2 * t + 8);
        }
    }

    // ---- cp.async loader mapping (1x 16B K + 1x 16B V per thread/tile) ----
    int lkey = tid >> 2, lpart = tid & 3;
    int ld   = tid >> 3, lc    = tid & 7;
    const __nv_bfloat16* kgm =
        g_qkv + (size_t)(b * NTOK + lkey) * (3 * CH) + CH + h * HD + lpart * 8;
    const __nv_bfloat16* vgm =
        g_vT + ((size_t)bh * HD + ld) * NTOK + lc * 8;
    unsigned ksdst[2], vtdst[2];
    ksdst[0] = smem_u32(&Ks[0][lkey][lpart * 8]);
    ksdst[1] = smem_u32(&Ks[1][lkey][lpart * 8]);
    vtdst[0] = smem_u32(&VT[0][ld][lc * 8]);
    vtdst[1] = smem_u32(&VT[1][ld][lc * 8]);

    // ---- ldmatrix per-lane base addresses ----
    int q2 = lane >> 3, r8 = lane & 7;
    unsigned ks_lm[2], vt_lm[2], v1_lm[2];
    ks_lm[0] = smem_u32(&Ks[0][8 * (q2 >> 1) + r8][8 * (q2 & 1)]);
    ks_lm[1] = ks_lm[0] + 64 * 40 * 2;
    vt_lm[0] = smem_u32(&VT[0][8 * (q2 >> 1) + r8][8 * (q2 & 1)]);
    vt_lm[1] = vt_lm[0] + 40 * 72 * 2;
    v1_lm[0] = smem_u32(&VT[0][32 + r8][16 * (q2 >> 1) + 8 * (q2 & 1)]);
    v1_lm[1] = v1_lm[0] + 40 * 72 * 2;

    // prologue: load tile 0 into buffer 0
    CP16(ksdst[0], kgm);
    CP16(vtdst[0], vgm);
    CPCOMMIT();

    float oc[5][4] = {};
    int buf = 0;

    for (int j0 = 0; j0 < NTOK; j0 += 64) {
        CPWAIT0();
        __syncthreads();
        if (j0 + 64 < NTOK) {
            int nb = buf ^ 1;
            CP16(ksdst[nb], kgm + (size_t)(j0 + 64) * (3 * CH));
            CP16(vtdst[nb], vgm + j0 + 64);
            CPCOMMIT();
        }
        unsigned kb = ks_lm[buf];
        unsigned vb = vt_lm[buf];
        unsigned v1 = v1_lm[buf];

        // ---- S = Q K^T, p = exp2(S) packed to bf16x2 A-fragments ----
        unsigned pa[4][4];
#pragma unroll
        for (int jp = 0; jp < 4; jp++) {
            unsigned f0[4], f1[4];
            LDSM4(f0[0], f0[1], f0[2], f0[3], kb + jp * 1280);
            LDSM4(f1[0], f1[1], f1[2], f1[3], kb + jp * 1280 + 32);
#pragma unroll
            for (int jj = 0; jj < 2; jj++) {
                float s4[4] = {0.f, 0.f, 0.f, 0.f};
                mma16816(s4, qa[0], f0[2 * jj], f0[2 * jj + 1]);
                mma16816(s4, qa[1], f1[2 * jj], f1[2 * jj + 1]);
                __nv_bfloat162 lo = __floats2bfloat162_rn(s4[0], s4[1]);
                __nv_bfloat162 hi = __floats2bfloat162_rn(s4[2], s4[3]);
                pa[jp][2 * jj]     = ex2b(*(unsigned*)&lo);
                pa[jp][2 * jj + 1] = ex2b(*(unsigned*)&hi);
            }
        }

        // ---- O += P V (dims 0..31) ----
#pragma unroll
        for (int kk = 0; kk < 4; kk++) {
#pragma unroll
            for (int jdp = 0; jdp < 2; jdp++) {
                unsigned m[4];
                LDSM4(m[0], m[1], m[2], m[3], vb + jdp * 2304 + kk * 32);
                mma16816(oc[2 * jdp],     pa[kk], m[0], m[1]);
                mma16816(oc[2 * jdp + 1], pa[kk], m[2], m[3]);
            }
        }
        // ---- l += P (ones column, dims 32..39) ----
#pragma unroll
        for (int kkp = 0; kkp < 2; kkp++) {
            unsigned m[4];
            LDSM4(m[0], m[1], m[2], m[3], v1 + kkp * 64);
            mma16816(oc[4], pa[2 * kkp],     m[0], m[1]);
            mma16816(oc[4], pa[2 * kkp + 1], m[2], m[3]);
        }
        buf ^= 1;
    }

    // l lives in column 0 of the ones d-tile -> lanes with t==0; broadcast
    float l0 = __shfl_sync(0xffffffffu, oc[4][0], lane & ~3);
    float l1 = __shfl_sync(0xffffffffu, oc[4][2], lane & ~3);
    float inv0 = 1.0f / l0;
    float inv1 = 1.0f / l1;

    __nv_bfloat16* op0 = g_attn + (size_t)(b * NTOK + q0 + warp * 16 + g) * CH + h * HD;
    __nv_bfloat16* op1 = op0 + (size_t)8 * CH;
#pragma unroll
    for (int jd = 0; jd < 4; jd++) {
        __nv_bfloat162 r0 = __floats2bfloat162_rn(oc[jd][0] * inv0, oc[jd][1] * inv0);
        __nv_bfloat162 r1 = __floats2bfloat162_rn(oc[jd][2] * inv1, oc[jd][3] * inv1);
        *(__nv_bfloat162*)(op0 + 8 * jd + 2 * t) = r0;
        *(__nv_bfloat162*)(op1 + 8 * jd + 2 * t) = r1;
    }
}

// ---------------- launch ----------------
extern "C" void kernel_launch(void* const* d_in, const int* in_sizes, int n_in,
                              void* d_out, int out_size) {
    const float* x      = (const float*)d_in[0];
    const float* ln1_w  = (const float*)d_in[1];
    const float* ln1_b  = (const float*)d_in[2];
    const float* qkv_w  = (const float*)d_in[3];
    const float* proj_w = (const float*)d_in[4];
    const float* proj_b = (const float*)d_in[5];
    const float* ln2_w  = (const float*)d_in[6];
    const float* ln2_b  = (const float*)d_in[7];
    const float* fc1_w  = (const float*)d_in[8];
    const float* fc1_b  = (const float*)d_in[9];
    const float* fc2_w  = (const float*)d_in[10];
    const float* fc2_b  = (const float*)d_in[11];
    float* out = (float*)d_out;

    void *p_xln, *p_xtok, *p_attn, *p_x2, *p_hdn;
    void *p_wqkv, *p_wproj, *p_wfc1, *p_wfc2;
    cudaGetSymbolAddress(&p_xln,  g_xln);
    cudaGetSymbolAddress(&p_xtok, g_xtok);
    cudaGetSymbolAddress(&p_attn, g_attn);
    cudaGetSymbolAddress(&p_x2,   g_x2);
    cudaGetSymbolAddress(&p_hdn,  g_hdn);
    cudaGetSymbolAddress(&p_wqkv, g_wqkv);
    cudaGetSymbolAddress(&p_wproj, g_wproj);
    cudaGetSymbolAddress(&p_wfc1, g_wfc1);
    cudaGetSymbolAddress(&p_wfc2, g_wfc2);
    __nv_bfloat16* xln  = (__nv_bfloat16*)p_xln;
    float*         xtok = (float*)p_xtok;
    __nv_bfloat16* attn = (__nv_bfloat16*)p_attn;
    float*         x2   = (float*)p_x2;
    __nv_bfloat16* hdn  = (__nv_bfloat16*)p_hdn;
    __nv_bfloat16* wqkv = (__nv_bfloat16*)p_wqkv;
    __nv_bfloat16* wproj= (__nv_bfloat16*)p_wproj;
    __nv_bfloat16* wfc1 = (__nv_bfloat16*)p_wfc1;
    __nv_bfloat16* wfc2 = (__nv_bfloat16*)p_wfc2;

    // 0. weights -> bf16
    wconv_kernel<<<512, 256>>>(qkv_w, proj_w, fc1_w, fc2_w);

    // 1. LN1 (NCHW -> token-major bf16 + raw fp32 copy)
    ln1_kernel<<<BATCH * (NTOK / 32), 256>>>(x, ln1_w, ln1_b);

    // 2. QKV gemm (tensor cores) -> q/k in g_qkv, v in g_vT
    gemm_tc<0><<<dim3(3 * CH / 64, M_ROWS / 128), 256>>>(
        xln, wqkv, nullptr, nullptr, nullptr, CH);

    // 3. flash attention -> g_attn bf16
    attn_mma_kernel<<<dim3(NTOK / 128, BATCH * HEADS), 256>>>();

    // 4. proj + residual + LN2 fused -> x2 fp32 + xln bf16
    proj_ln_kernel<<<M_ROWS / 64, 256>>>(attn, wproj, proj_b, xtok, ln2_w, ln2_b);

    // 5. fc1 + bias + gelu -> hdn bf16
    gemm_tc<2><<<dim3(HIDDEN / 64, M_ROWS / 128), 256>>>(
        xln, wfc1, fc1_b, nullptr, nullptr, CH);

    // 6. fc2 + bias + residual(x2) -> out (NCHW fp32)
    gemm_tc<3><<<dim3(CH / 64, M_ROWS / 128), 256>>>(
        hdn, wfc2, fc2_b, x2, out, HIDDEN);
}